// round 16
// baseline (speedup 1.0000x reference)
#include <cuda_runtime.h>
#include <cuda_bf16.h>
#include <cstdint>

#define CHARS 128
#define CE    64
#define HE    128
#define GE    512
#define WE    256
#define HP    256
#define GP    1024
#define KIN   384
#define TAGS  50
#define NW    8192
#define MAXC  16

__device__ float g_table[CHARS * GE];
__device__ float g_hchar[NW * HE];
__device__ float g_xgp[NW * GP];
__device__ float g_hs[NW * HP];

__device__ __forceinline__ float sigmf(float x) { return __fdividef(1.0f, 1.0f + __expf(-x)); }
__device__ __forceinline__ float tanh_fast(float x) {
    return __fdividef(2.0f, 1.0f + __expf(-2.0f * x)) - 1.0f;
}

// ---- K1: per-char-id input projection table + biases ----
__global__ void k_table(const float* __restrict__ ce_emb, const float* __restrict__ Wih,
                        const float* __restrict__ bih, const float* __restrict__ bhh) {
    __shared__ float ce[CE];
    int c = blockIdx.x;
    if (threadIdx.x < CE) ce[threadIdx.x] = ce_emb[c * CE + threadIdx.x];
    __syncthreads();
    int g = threadIdx.x;
    float acc = bih[g] + bhh[g];
    const float* wr = Wih + g * CE;
#pragma unroll
    for (int k = 0; k < CE; k++) acc += ce[k] * wr[k];
    g_table[c * GE + g] = acc;
}

// ---- K2: batched char LSTM, 16 words/block ----
#define K2S 520
__global__ __launch_bounds__(256) void k_char(const float* __restrict__ Whh,
                                              const int* __restrict__ char_ids,
                                              const int* __restrict__ char_len) {
    extern __shared__ float sm[];
    float* w_tile = sm;                  // 32 x K2S
    float* h_s = sm + 32 * K2S;          // 16 x 128
    int* cid_s = (int*)(h_s + 16 * HE);  // 16
    int* len_s = cid_s + 16;             // 16

    int tid = threadIdx.x;
    int tc = tid & 63;
    int tw = tid >> 6;
    int w0 = blockIdx.x * 16;

    for (int i = tid; i < 16 * HE; i += 256) h_s[i] = 0.0f;
    if (tid < 16) len_s[tid] = char_len[w0 + tid];

    float cc[4][2];
#pragma unroll
    for (int i = 0; i < 4; i++) { cc[i][0] = 0.f; cc[i][1] = 0.f; }
    __syncthreads();

    for (int t = 0; t < MAXC; t++) {
        float acc[4][2][4];
#pragma unroll
        for (int a = 0; a < 4; a++)
#pragma unroll
            for (int b = 0; b < 2; b++)
#pragma unroll
                for (int d = 0; d < 4; d++) acc[a][b][d] = 0.f;

        for (int ch = 0; ch < 4; ch++) {
            int k0 = ch * 32;
            __syncthreads();
            for (int idx = tid; idx < GE * 32; idx += 256) {
                int g = idx >> 5, kk = idx & 31;
                w_tile[kk * K2S + g] = Whh[g * HE + k0 + kk];
            }
            if (ch == 0 && tid < 16) cid_s[tid] = char_ids[(w0 + tid) * MAXC + t];
            __syncthreads();
            for (int kk = 0; kk < 32; kk++) {
                float hv[4];
#pragma unroll
                for (int i = 0; i < 4; i++) hv[i] = h_s[(tw * 4 + i) * HE + k0 + kk];
                const float* wr = w_tile + kk * K2S;
#pragma unroll
                for (int tau = 0; tau < 4; tau++) {
                    float2 wv = *(const float2*)(wr + tau * HE + tc * 2);
#pragma unroll
                    for (int i = 0; i < 4; i++) {
                        acc[tau][0][i] += hv[i] * wv.x;
                        acc[tau][1][i] += hv[i] * wv.y;
                    }
                }
            }
        }
        __syncthreads();
#pragma unroll
        for (int i = 0; i < 4; i++) {
            int w = tw * 4 + i;
            if (t < len_s[w]) {
                const float* tr = g_table + cid_s[w] * GE;
#pragma unroll
                for (int j = 0; j < 2; j++) {
                    int jj = tc * 2 + j;
                    float gi = acc[0][j][i] + tr[jj];
                    float gf = acc[1][j][i] + tr[HE + jj];
                    float gg = acc[2][j][i] + tr[2 * HE + jj];
                    float go = acc[3][j][i] + tr[3 * HE + jj];
                    float cn = sigmf(gf) * cc[i][j] + sigmf(gi) * tanhf(gg);
                    cc[i][j] = cn;
                    h_s[w * HE + jj] = sigmf(go) * tanhf(cn);
                }
            }
        }
    }
#pragma unroll
    for (int i = 0; i < 4; i++) {
        int w = tw * 4 + i;
#pragma unroll
        for (int j = 0; j < 2; j++)
            g_hchar[(w0 + w) * HE + tc * 2 + j] = h_s[w * HE + tc * 2 + j];
    }
}

// ---- K3: word-LSTM input projection GEMM [8192,384]x[384,1024] ----
__global__ __launch_bounds__(256) void k_feat(const float* __restrict__ word_emb,
                                              const float* __restrict__ Wih,
                                              const float* __restrict__ bih,
                                              const float* __restrict__ bhh,
                                              const int* __restrict__ sentence) {
    __shared__ float a_tile[16 * 33];
    __shared__ float w_tile[32 * 264];
    __shared__ int sent_s[16];

    int tid = threadIdx.x;
    int tg = tid & 63;
    int tn = tid >> 6;
    int n0 = blockIdx.x * 16;
    int g0 = blockIdx.y * 256;

    if (tid < 16) sent_s[tid] = sentence[n0 + tid];

    float acc[4][4];
#pragma unroll
    for (int i = 0; i < 4; i++)
#pragma unroll
        for (int j = 0; j < 4; j++) acc[i][j] = 0.f;

    for (int kc = 0; kc < 12; kc++) {
        int k0 = kc * 32;
        __syncthreads();
        int idx = tid;
#pragma unroll
        for (int rep = 0; rep < 2; rep++, idx += 256) {
            int n = idx >> 5, kk = idx & 31;
            int k = k0 + kk;
            float v;
            if (k < WE) v = word_emb[(size_t)sent_s[n] * WE + k];
            else v = g_hchar[(n0 + n) * HE + (k - WE)];
            a_tile[n * 33 + kk] = v;
        }
        for (int j = tid; j < 256 * 32; j += 256) {
            int g = j >> 5, kk = j & 31;
            w_tile[kk * 264 + g] = Wih[(size_t)(g0 + g) * KIN + k0 + kk];
        }
        __syncthreads();
        for (int kk = 0; kk < 32; kk++) {
            float4 wv = *(const float4*)(w_tile + kk * 264 + tg * 4);
            float av[4];
#pragma unroll
            for (int i = 0; i < 4; i++) av[i] = a_tile[(tn * 4 + i) * 33 + kk];
#pragma unroll
            for (int i = 0; i < 4; i++) {
                acc[i][0] += av[i] * wv.x;
                acc[i][1] += av[i] * wv.y;
                acc[i][2] += av[i] * wv.z;
                acc[i][3] += av[i] * wv.w;
            }
        }
    }
    float bias[4];
#pragma unroll
    for (int j = 0; j < 4; j++) {
        int gg = g0 + tg * 4 + j;
        bias[j] = bih[gg] + bhh[gg];
    }
#pragma unroll
    for (int i = 0; i < 4; i++) {
        int n = n0 + tn * 4 + i;
        float4 o;
        o.x = acc[i][0] + bias[0];
        o.y = acc[i][1] + bias[1];
        o.z = acc[i][2] + bias[2];
        o.w = acc[i][3] + bias[3];
        *(float4*)(g_xgp + (size_t)n * GP + g0 + tg * 4) = o;
    }
}

// ---- K4 v2b: sequential word LSTM, 8-CTA cluster ----
// Gate-broadcast + redundant epilogue; ping-pong mbarrier pair (race-hardened).
__global__ void __cluster_dims__(8, 1, 1) __launch_bounds__(256, 1)
k_word(const float* __restrict__ Whh, int N) {
    __shared__ __align__(16) float h_s[HP];
    __shared__ __align__(16) float gbuf[2][4 * HP];
    __shared__ __align__(16) unsigned long long mbar_store[2];

    int tid = threadIdx.x;
    int r = blockIdx.x;          // cluster rank
    int row = tid >> 1;          // local gate row 0..127
    int half = tid & 1;          // k-half
    int tau = row >> 5;          // gate type
    int jj = row & 31;           // local unit
    int U = r * 32 + jj;         // global unit
    int G = tau * HP + U;        // global gate row (i,f,g,o major)

    // 128 weights per thread, packed as 64 x f32x2
    unsigned long long w2[64];
    {
        const ulonglong2* wp = (const ulonglong2*)(Whh + (size_t)G * HP + half * 128);
#pragma unroll
        for (int i = 0; i < 32; i++) { ulonglong2 v = wp[i]; w2[2 * i] = v.x; w2[2 * i + 1] = v.y; }
    }

    for (int i = tid; i < HP; i += 256) h_s[i] = 0.f;
    uint32_t mb0 = (uint32_t)__cvta_generic_to_shared(&mbar_store[0]);
    uint32_t mb1 = (uint32_t)__cvta_generic_to_shared(&mbar_store[1]);
    if (tid == 0) {
        asm volatile("mbarrier.init.shared.b64 [%0], %1;" :: "r"(mb0), "r"(8) : "memory");
        asm volatile("mbarrier.init.shared.b64 [%0], %1;" :: "r"(mb1), "r"(8) : "memory");
    }
    float c = 0.f;   // cell state for unit `tid` (replicated across CTAs)
    __syncthreads();
    asm volatile("barrier.cluster.arrive.aligned;\n\tbarrier.cluster.wait.aligned;" ::: "memory");

    // precompute DSMEM addresses (loop-invariant)
    uint32_t gb_peer[2][8];
    {
        uint32_t g0l = (uint32_t)__cvta_generic_to_shared(&gbuf[0][G]);
        uint32_t g1l = (uint32_t)__cvta_generic_to_shared(&gbuf[1][G]);
#pragma unroll
        for (int p = 0; p < 8; p++) {
            asm("mapa.shared::cluster.u32 %0, %1, %2;" : "=r"(gb_peer[0][p]) : "r"(g0l), "r"(p));
            asm("mapa.shared::cluster.u32 %0, %1, %2;" : "=r"(gb_peer[1][p]) : "r"(g1l), "r"(p));
        }
    }
    uint32_t mb_peer0 = 0, mb_peer1 = 0;
    if (tid < 8) {
        asm("mapa.shared::cluster.u32 %0, %1, %2;" : "=r"(mb_peer0) : "r"(mb0), "r"(tid));
        asm("mapa.shared::cluster.u32 %0, %1, %2;" : "=r"(mb_peer1) : "r"(mb1), "r"(tid));
    }

    for (int n = 0; n < N; n++) {
        int buf = n & 1;
        float xgv = (half == 0) ? __ldg(&g_xgp[(size_t)n * GP + G]) : 0.f;

        // matvec over this thread's k-half (128 k) with packed f32x2 FMA
        const ulonglong2* hp = (const ulonglong2*)(h_s + half * 128);
        unsigned long long a0 = 0ull, a1 = 0ull;
#pragma unroll
        for (int i = 0; i < 32; i++) {
            ulonglong2 hv = hp[i];
            asm("fma.rn.f32x2 %0, %1, %2, %0;" : "+l"(a0) : "l"(w2[2 * i]), "l"(hv.x));
            asm("fma.rn.f32x2 %0, %1, %2, %0;" : "+l"(a1) : "l"(w2[2 * i + 1]), "l"(hv.y));
        }
        float v = (__uint_as_float((unsigned)a0) + __uint_as_float((unsigned)(a0 >> 32)))
                + (__uint_as_float((unsigned)a1) + __uint_as_float((unsigned)(a1 >> 32)));
        v += __shfl_down_sync(0xffffffffu, v, 1);   // combine k-halves -> even lane

        if (half == 0) {
            float gv = v + xgv;
#pragma unroll
            for (int p = 0; p < 8; p++)
                asm volatile("st.shared::cluster.f32 [%0], %1;"
                             :: "r"(gb_peer[buf][p]), "f"(gv) : "memory");
        }
        __syncthreads();   // all CTA stores issued before the release-arrive
        if (tid < 8)
            asm volatile("mbarrier.arrive.release.cluster.shared::cluster.b64 _, [%0];"
                         :: "r"(buf ? mb_peer1 : mb_peer0) : "memory");
        {
            int par = (n >> 1) & 1;   // each barrier used every 2nd step
            uint32_t mbw = buf ? mb1 : mb0;
            asm volatile(
                "{\n\t.reg .pred P;\n"
                "WLP%=:\n\t"
                "mbarrier.try_wait.parity.acquire.cluster.shared::cta.b64 P, [%0], %1, 0x989680;\n\t"
                "@P bra WDN%=;\n\t"
                "bra WLP%=;\n"
                "WDN%=:\n\t}"
                :: "r"(mbw), "r"(par) : "memory");
        }
        // epilogue: every thread owns one unit u = tid (redundant across CTAs)
        {
            float gi = gbuf[buf][tid];
            float gf = gbuf[buf][HP + tid];
            float gg = gbuf[buf][2 * HP + tid];
            float go = gbuf[buf][3 * HP + tid];
            float cn = sigmf(gf) * c + sigmf(gi) * tanh_fast(gg);
            c = cn;
            float hv2 = sigmf(go) * tanh_fast(cn);
            h_s[tid] = hv2;
            if (r == 0) g_hs[(size_t)n * HP + tid] = hv2;
        }
        __syncthreads();   // h_s complete before next matvec
    }
}

// ---- K5: tag projection + log_softmax ----
__global__ __launch_bounds__(256) void k_tag(const float* __restrict__ Wt,
                                             const float* __restrict__ bt_g,
                                             float* __restrict__ out) {
    extern __shared__ float sm2[];
    float* wt = sm2;                 // 50 * 257
    float* hrow = wt + TAGS * 257;   // 32 * 256
    float* lg = hrow + 32 * HP;      // 32 * 52
    float* bt = lg + 32 * 52;        // 50
    float* lse_s = bt + TAGS;        // 32

    int tid = threadIdx.x;
    int r0 = blockIdx.x * 32;

    for (int i = tid; i < TAGS * HP; i += 256) {
        int t = i / HP, k = i - t * HP;
        wt[t * 257 + k] = Wt[i];
    }
    for (int i = tid; i < 32 * HP; i += 256) hrow[i] = g_hs[(size_t)r0 * HP + i];
    if (tid < TAGS) bt[tid] = bt_g[tid];
    __syncthreads();

    for (int idx = tid; idx < 32 * TAGS; idx += 256) {
        int rr = idx / TAGS, t = idx - rr * TAGS;
        float a = bt[t];
        const float* hh = hrow + rr * HP;
        const float* ww = wt + t * 257;
#pragma unroll 8
        for (int k = 0; k < HP; k++) a += hh[k] * ww[k];
        lg[rr * 52 + t] = a;
    }
    __syncthreads();
    if (tid < 32) {
        float mx = -1e30f;
        for (int t = 0; t < TAGS; t++) mx = fmaxf(mx, lg[tid * 52 + t]);
        float s = 0.f;
        for (int t = 0; t < TAGS; t++) s += __expf(lg[tid * 52 + t] - mx);
        lse_s[tid] = mx + logf(s);
    }
    __syncthreads();
    for (int idx = tid; idx < 32 * TAGS; idx += 256) {
        int rr = idx / TAGS, t = idx - rr * TAGS;
        out[(size_t)(r0 + rr) * TAGS + t] = lg[rr * 52 + t] - lse_s[rr];
    }
}

extern "C" void kernel_launch(void* const* d_in, const int* in_sizes, int n_in,
                              void* d_out, int out_size) {
    const float* char_emb = (const float*)d_in[0];
    const float* word_emb = (const float*)d_in[1];
    const float* Wih_e = (const float*)d_in[2];
    const float* Whh_e = (const float*)d_in[3];
    const float* bih_e = (const float*)d_in[4];
    const float* bhh_e = (const float*)d_in[5];
    const float* Wih_p = (const float*)d_in[6];
    const float* Whh_p = (const float*)d_in[7];
    const float* bih_p = (const float*)d_in[8];
    const float* bhh_p = (const float*)d_in[9];
    const float* W_tag = (const float*)d_in[10];
    const float* b_tag = (const float*)d_in[11];
    const int* sentence = (const int*)d_in[12];
    const int* char_ids = (const int*)d_in[13];
    const int* char_lengths = (const int*)d_in[14];
    float* out = (float*)d_out;

    cudaFuncSetAttribute(k_char, cudaFuncAttributeMaxDynamicSharedMemorySize,
                         (32 * K2S + 16 * HE) * 4 + 32 * 4);
    cudaFuncSetAttribute(k_tag, cudaFuncAttributeMaxDynamicSharedMemorySize,
                         (TAGS * 257 + 32 * HP + 32 * 52 + TAGS + 32) * 4);

    k_table<<<CHARS, GE>>>(char_emb, Wih_e, bih_e, bhh_e);
    k_char<<<NW / 16, 256, (32 * K2S + 16 * HE) * 4 + 32 * 4>>>(Whh_e, char_ids, char_lengths);
    dim3 fg(NW / 16, GP / 256);
    k_feat<<<fg, 256>>>(word_emb, Wih_p, bih_p, bhh_p, sentence);
    k_word<<<8, 256>>>(Whh_p, NW);
    k_tag<<<NW / 32, 256, (TAGS * 257 + 32 * HP + 32 * 52 + TAGS + 32) * 4>>>(W_tag, b_tag, out);
}